// round 4
// baseline (speedup 1.0000x reference)
#include <cuda_runtime.h>
#include <math.h>

#define BB 32
#define CC 64
#define TT_ 128
#define VV 25
#define RR 8
#define TS 9
#define OUTC 64
#define TV 3200   // TT_*VV

typedef unsigned long long u64;

// scratch (allocation-free rule: device globals)
__device__ float g_xm[BB * CC * VV];                 // mean_t x
__device__ float g_dbuf[BB * RR * VV * VV];          // d[b,r,j,i]
__device__ float g_zbuf[(size_t)BB * CC * TT_ * VV]; // z[b,c,t,i]

__device__ __forceinline__ u64 pack2(float lo, float hi) {
    u64 r;
    asm("mov.b64 %0, {%1, %2};" : "=l"(r) : "f"(lo), "f"(hi));
    return r;
}
__device__ __forceinline__ void ffma2(u64& d, u64 a, u64 b) {
    asm("fma.rn.f32x2 %0, %1, %2, %0;" : "+l"(d) : "l"(a), "l"(b));
}
__device__ __forceinline__ float lo32(u64 v) { float a,b; asm("mov.b64 {%0,%1}, %2;" : "=f"(a), "=f"(b) : "l"(v)); return a; }
__device__ __forceinline__ float hi32(u64 v) { float a,b; asm("mov.b64 {%0,%1}, %2;" : "=f"(a), "=f"(b) : "l"(v)); return b; }

// ---------------- kA1: coalesced mean over T, one block per (b,c) ----------------
__global__ void __launch_bounds__(128) kA1(const float* __restrict__ x) {
    int c = blockIdx.x, b = blockIdx.y;
    int tid = threadIdx.x;
    __shared__ float xt[TT_ * VV];
    __shared__ float part[VV * 4];

    const float* xp = x + (size_t)(b * CC + c) * TV;
    for (int i = tid; i < TT_ * VV; i += 128) xt[i] = xp[i];
    __syncthreads();

    if (tid < VV * 4) {
        int v = tid >> 2, s = tid & 3;
        float acc = 0.f;
#pragma unroll 8
        for (int t = s; t < TT_; t += 4) acc += xt[t * VV + v];
        part[tid] = acc;
    }
    __syncthreads();
    if (tid < VV) {
        float m = (part[tid * 4] + part[tid * 4 + 1] + part[tid * 4 + 2] + part[tid * 4 + 3]) * (1.f / (float)TT_);
        g_xm[(b * CC + c) * VV + tid] = m;
    }
}

// ---------------- kA2: x1/x2 + d=tanh(x1-x2), one block per b ----------------
__global__ void __launch_bounds__(256) kA2(const float* __restrict__ w1, const float* __restrict__ b1,
                                           const float* __restrict__ w2, const float* __restrict__ b2) {
    int b = blockIdx.x;
    int tid = threadIdx.x;
    __shared__ float xm[CC * VV];
    __shared__ float x1s[RR * VV];
    __shared__ float x2s[RR * VV];

    const float* xmg = g_xm + b * (CC * VV);
    for (int i = tid; i < CC * VV; i += 256) xm[i] = xmg[i];
    __syncthreads();

    for (int q = tid; q < 2 * RR * VV; q += 256) {
        int which = q / (RR * VV);
        int idx = q % (RR * VV);
        int r = idx / VV, v = idx % VV;
        const float* w = which ? w2 : w1;
        float s = 0.f;
#pragma unroll 8
        for (int c = 0; c < CC; c++) s = fmaf(w[r * CC + c], xm[c * VV + v], s);
        s += (which ? b2 : b1)[r];
        (which ? x2s : x1s)[idx] = s;
    }
    __syncthreads();

    float* db = g_dbuf + b * (RR * VV * VV);
    for (int idx = tid; idx < RR * VV * VV; idx += 256) {
        int r = idx / (VV * VV);
        int rem = idx % (VV * VV);
        int j = rem / VV, i = rem % VV;
        db[idx] = tanhf(x1s[r * VV + j] - x2s[r * VV + i]);
    }
}

// ---------------- kB: build W (duplicated float2) + dynamic conv (f32x2) -> z ----------------
// 512 threads, warp w owns t in [w*8, w*8+8). lane<25 owns output vertex i.
__global__ void __launch_bounds__(512) kB(const float* __restrict__ x,
                                          const float* __restrict__ A,
                                          const float* __restrict__ w4, const float* __restrict__ b4) {
    int c = blockIdx.x;
    int b = blockIdx.y;
    int tid = threadIdx.x;

    __shared__ __align__(16) float2 W2s[VV * TS * VV];  // [j][k][i] duplicated, 45KB
    __shared__ __align__(16) float xsT[VV * 140];       // [j][pad-time], stride 140

    const float* db = g_dbuf + b * (RR * VV * VV);

    // W[j,i,k] = A[j,i] + b4[c*9+k] + sum_r w4[c*9+k, r] * d[r,j,i]
    for (int p = tid; p < VV * VV; p += 512) {
        float dr[RR];
#pragma unroll
        for (int r = 0; r < RR; r++) dr[r] = __ldg(db + r * (VV * VV) + p);
        float a = __ldg(A + p);
        int j = p / VV, i = p % VV;
#pragma unroll
        for (int k = 0; k < TS; k++) {
            int o = c * TS + k;
            float s = a + __ldg(b4 + o);
#pragma unroll
            for (int r = 0; r < RR; r++) s = fmaf(__ldg(w4 + o * RR + r), dr[r], s);
            W2s[(j * TS + k) * VV + i] = make_float2(s, s);
        }
    }

    // stage x transposed + causal left pad (8 zeros)
    for (int idx = tid; idx < VV * 8; idx += 512) {
        int j = idx / 8, s0 = idx % 8;
        xsT[j * 140 + s0] = 0.f;
    }
    const float* xp = x + (size_t)(b * CC + c) * TV;
    for (int idx = tid; idx < TT_ * VV; idx += 512) {
        int t = idx / VV, j = idx % VV;
        xsT[j * 140 + t + 8] = xp[idx];
    }
    __syncthreads();

    int warp = tid >> 5, lane = tid & 31;
    int t0 = warp * 8;  // 16 warps * 8 t = 128

    if (lane < VV) {
        u64 acc[4];
#pragma unroll
        for (int p = 0; p < 4; p++) acc[p] = 0ULL;

        const u64* wbase = reinterpret_cast<const u64*>(W2s) + lane;

        for (int j = 0; j < VV; j++) {
            // 16 consecutive padded-time samples (warp-uniform -> broadcast LDS.128)
            float xr[16];
            const float4* xv = reinterpret_cast<const float4*>(&xsT[j * 140 + t0]);
#pragma unroll
            for (int q = 0; q < 4; q++) {
                float4 v = xv[q];
                xr[4 * q + 0] = v.x; xr[4 * q + 1] = v.y;
                xr[4 * q + 2] = v.z; xr[4 * q + 3] = v.w;
            }
            u64 pr[15];
#pragma unroll
            for (int m = 0; m < 15; m++) pr[m] = pack2(xr[m], xr[m + 1]);

            const u64* wrow = wbase + (j * TS) * VV;
#pragma unroll
            for (int k = 0; k < TS; k++) {
                u64 w2 = wrow[k * VV];  // per-lane LDS.64, duplicated pair
#pragma unroll
                for (int p = 0; p < 4; p++) ffma2(acc[p], pr[2 * p + k], w2);
            }
        }
        float* zp = g_zbuf + (size_t)(b * CC + c) * TV + lane;
#pragma unroll
        for (int p = 0; p < 4; p++) {
            zp[(t0 + 2 * p) * VV] = lo32(acc[p]);
            zp[(t0 + 2 * p + 1) * VV] = hi32(acc[p]);
        }
    }
}

// ---------------- kC: out = w3 @ z + b3, register-tiled outer product ----------------
// Block: 64 o x 128 tv. 256 threads = 8 warps; warp <-> 8 o's (o0=warp*8),
// lane <-> 4 tv (tv = tvblk + lane*4). Accumulators packed over (o,o+1) pairs:
// w-pair natural from contiguous w3T[c][o] (broadcast LDS), x dup-packed.
__global__ void __launch_bounds__(256) kC(const float* __restrict__ w3, const float* __restrict__ b3,
                                          float* __restrict__ out) {
    int b = blockIdx.y;
    int tv0 = blockIdx.x * 128;
    int tid = threadIdx.x;
    int warp = tid >> 5, lane = tid & 31;

    __shared__ __align__(16) float zs[CC * 128];    // 32KB [c][tv]
    __shared__ __align__(16) float w3T[CC * OUTC];  // 16KB [c][o]

    const float* zb = g_zbuf + (size_t)b * CC * TV;
    for (int i = tid; i < CC * 32; i += 256) {          // 2048 float4 loads
        int c = i >> 5, u4 = i & 31;
        *reinterpret_cast<float4*>(&zs[c * 128 + u4 * 4]) =
            *reinterpret_cast<const float4*>(zb + c * TV + tv0 + u4 * 4);
    }
    for (int i = tid; i < CC * OUTC; i += 256) {
        int o = i >> 6, c = i & 63;                     // read w3 coalesced [o][c]
        w3T[c * OUTC + o] = w3[i];
    }
    __syncthreads();

    int o0 = warp * 8;
    // acc[op][q]: op = o-pair 0..3 (o0+2op, o0+2op+1), q = tv 0..3
    u64 acc[4][4];
#pragma unroll
    for (int op = 0; op < 4; op++) {
        u64 bp = pack2(__ldg(b3 + o0 + 2 * op), __ldg(b3 + o0 + 2 * op + 1));
#pragma unroll
        for (int q = 0; q < 4; q++) acc[op][q] = bp;
    }

    const float* zrow = &zs[lane * 4];
#pragma unroll 4
    for (int c = 0; c < CC; c++) {
        float4 xv = *reinterpret_cast<const float4*>(zrow + c * 128);   // per-lane LDS.128
        u64 xd0 = pack2(xv.x, xv.x);
        u64 xd1 = pack2(xv.y, xv.y);
        u64 xd2 = pack2(xv.z, xv.z);
        u64 xd3 = pack2(xv.w, xv.w);
        const u64* wrow = reinterpret_cast<const u64*>(&w3T[c * OUTC + o0]);  // broadcast
        u64 w01 = wrow[0], w23 = wrow[1], w45 = wrow[2], w67 = wrow[3];
        ffma2(acc[0][0], xd0, w01); ffma2(acc[0][1], xd1, w01);
        ffma2(acc[0][2], xd2, w01); ffma2(acc[0][3], xd3, w01);
        ffma2(acc[1][0], xd0, w23); ffma2(acc[1][1], xd1, w23);
        ffma2(acc[1][2], xd2, w23); ffma2(acc[1][3], xd3, w23);
        ffma2(acc[2][0], xd0, w45); ffma2(acc[2][1], xd1, w45);
        ffma2(acc[2][2], xd2, w45); ffma2(acc[2][3], xd3, w45);
        ffma2(acc[3][0], xd0, w67); ffma2(acc[3][1], xd1, w67);
        ffma2(acc[3][2], xd2, w67); ffma2(acc[3][3], xd3, w67);
    }

    // epilogue: per o-row build float4 and STG.128 (coalesced)
    float* ob = out + (size_t)b * OUTC * TV + tv0 + lane * 4;
#pragma unroll
    for (int op = 0; op < 4; op++) {
        float4 lo, hi;
        lo.x = lo32(acc[op][0]); lo.y = lo32(acc[op][1]);
        lo.z = lo32(acc[op][2]); lo.w = lo32(acc[op][3]);
        hi.x = hi32(acc[op][0]); hi.y = hi32(acc[op][1]);
        hi.z = hi32(acc[op][2]); hi.w = hi32(acc[op][3]);
        *reinterpret_cast<float4*>(ob + (size_t)(o0 + 2 * op) * TV) = lo;
        *reinterpret_cast<float4*>(ob + (size_t)(o0 + 2 * op + 1) * TV) = hi;
    }
}

extern "C" void kernel_launch(void* const* d_in, const int* in_sizes, int n_in,
                              void* d_out, int out_size) {
    const float* x  = (const float*)d_in[0];
    const float* A  = (const float*)d_in[1];
    const float* w1 = (const float*)d_in[2];
    const float* b1 = (const float*)d_in[3];
    const float* w2 = (const float*)d_in[4];
    const float* b2 = (const float*)d_in[5];
    const float* w3 = (const float*)d_in[6];
    const float* b3 = (const float*)d_in[7];
    const float* w4 = (const float*)d_in[8];
    const float* b4 = (const float*)d_in[9];
    float* out = (float*)d_out;

    kA1<<<dim3(CC, BB), 128>>>(x);
    kA2<<<BB, 256>>>(w1, b1, w2, b2);
    kB<<<dim3(CC, BB), 512>>>(x, A, w4, b4);
    kC<<<dim3(TV / 128, BB), 256>>>(w3, b3, out);
}

// round 6
// speedup vs baseline: 1.1437x; 1.1437x over previous
#include <cuda_runtime.h>
#include <math.h>

#define BB 32
#define CC 64
#define TT_ 128
#define VV 25
#define RR 8
#define TS 9
#define OUTC 64
#define TV 3200   // TT_*VV

typedef unsigned long long u64;

// scratch (allocation-free rule: device globals)
__device__ float g_xm[BB * CC * VV];                 // mean_t x
__device__ float g_dbuf[BB * RR * VV * VV];          // d[b,r,j,i]
__device__ float g_zbuf[(size_t)BB * CC * TT_ * VV]; // z[b,c,t,i]

__device__ __forceinline__ u64 pack2(float lo, float hi) {
    u64 r;
    asm("mov.b64 %0, {%1, %2};" : "=l"(r) : "f"(lo), "f"(hi));
    return r;
}
__device__ __forceinline__ void ffma2(u64& d, u64 a, u64 b) {
    asm("fma.rn.f32x2 %0, %1, %2, %0;" : "+l"(d) : "l"(a), "l"(b));
}
__device__ __forceinline__ float lo32(u64 v) { float a,b; asm("mov.b64 {%0,%1}, %2;" : "=f"(a), "=f"(b) : "l"(v)); return a; }
__device__ __forceinline__ float hi32(u64 v) { float a,b; asm("mov.b64 {%0,%1}, %2;" : "=f"(a), "=f"(b) : "l"(v)); return b; }

// ---------------- kA1: coalesced mean over T, one block per (b,c) ----------------
__global__ void __launch_bounds__(128) kA1(const float* __restrict__ x) {
    int c = blockIdx.x, b = blockIdx.y;
    int tid = threadIdx.x;
    __shared__ float xt[TT_ * VV];
    __shared__ float part[VV * 4];

    const float* xp = x + (size_t)(b * CC + c) * TV;
    for (int i = tid; i < TT_ * VV; i += 128) xt[i] = xp[i];
    __syncthreads();

    if (tid < VV * 4) {
        int v = tid >> 2, s = tid & 3;
        float acc = 0.f;
#pragma unroll 8
        for (int t = s; t < TT_; t += 4) acc += xt[t * VV + v];
        part[tid] = acc;
    }
    __syncthreads();
    if (tid < VV) {
        float m = (part[tid * 4] + part[tid * 4 + 1] + part[tid * 4 + 2] + part[tid * 4 + 3]) * (1.f / (float)TT_);
        g_xm[(b * CC + c) * VV + tid] = m;
    }
}

// ---------------- kA2: x1/x2 + d=tanh(x1-x2), one block per b ----------------
__global__ void __launch_bounds__(256) kA2(const float* __restrict__ w1, const float* __restrict__ b1,
                                           const float* __restrict__ w2, const float* __restrict__ b2) {
    int b = blockIdx.x;
    int tid = threadIdx.x;
    __shared__ float xm[CC * VV];
    __shared__ float x1s[RR * VV];
    __shared__ float x2s[RR * VV];

    const float* xmg = g_xm + b * (CC * VV);
    for (int i = tid; i < CC * VV; i += 256) xm[i] = xmg[i];
    __syncthreads();

    for (int q = tid; q < 2 * RR * VV; q += 256) {
        int which = q / (RR * VV);
        int idx = q % (RR * VV);
        int r = idx / VV, v = idx % VV;
        const float* w = which ? w2 : w1;
        float s = 0.f;
#pragma unroll 8
        for (int c = 0; c < CC; c++) s = fmaf(w[r * CC + c], xm[c * VV + v], s);
        s += (which ? b2 : b1)[r];
        (which ? x2s : x1s)[idx] = s;
    }
    __syncthreads();

    float* db = g_dbuf + b * (RR * VV * VV);
    for (int idx = tid; idx < RR * VV * VV; idx += 256) {
        int r = idx / (VV * VV);
        int rem = idx % (VV * VV);
        int j = rem / VV, i = rem % VV;
        db[idx] = tanhf(x1s[r * VV + j] - x2s[r * VV + i]);
    }
}

// ---------------- kB: dynamic conv, zero-MOV f32x2 via dual (normal+shifted) x copies ----
// 256 threads (8 warps), warp w owns t in [w*16, w*16+16). lane<25 owns vertex i.
__global__ void __launch_bounds__(256) kB(const float* __restrict__ x,
                                          const float* __restrict__ A,
                                          const float* __restrict__ w4, const float* __restrict__ b4) {
    int c = blockIdx.x;
    int b = blockIdx.y;
    int tid = threadIdx.x;

    __shared__ __align__(16) float2 W2s[VV * TS * VV];  // [j][k][i] duplicated, 45KB
    __shared__ __align__(16) float xsT[VV * 140];       // [j][s] = xpad[s],   14KB
    __shared__ __align__(16) float xsS[VV * 140];       // [j][s] = xpad[s+1], 14KB

    const float* db = g_dbuf + b * (RR * VV * VV);

    // W[j,i,k] = A[j,i] + b4[c*9+k] + sum_r w4[c*9+k, r] * d[r,j,i], stored duplicated
    for (int p = tid; p < VV * VV; p += 256) {
        float dr[RR];
#pragma unroll
        for (int r = 0; r < RR; r++) dr[r] = __ldg(db + r * (VV * VV) + p);
        float a = __ldg(A + p);
        int j = p / VV, i = p % VV;
#pragma unroll
        for (int k = 0; k < TS; k++) {
            int o = c * TS + k;
            float s = a + __ldg(b4 + o);
#pragma unroll
            for (int r = 0; r < RR; r++) s = fmaf(__ldg(w4 + o * RR + r), dr[r], s);
            W2s[(j * TS + k) * VV + i] = make_float2(s, s);
        }
    }

    // stage x: xsT[j][8+t] = x[t][j] (zeros on [0,8) and [136,140));
    //          xsS[j][7+t] = x[t][j] (zeros on [0,7) and [135,140)).
    // FIX (R5): zero xsS ONLY on [0,7) — index 7 is DATA (x[0]); zeroing it raced
    // with the staging write below (no sync between the loops).
    for (int idx = tid; idx < VV * 8; idx += 256) {
        int j = idx / 8, s0 = idx % 8;
        xsT[j * 140 + s0] = 0.f;
        if (s0 < 7) xsS[j * 140 + s0] = 0.f;
        if (s0 == 0) {
            xsS[j * 140 + 135] = 0.f;
#pragma unroll
            for (int q = 136; q < 140; q++) { xsT[j * 140 + q] = 0.f; xsS[j * 140 + q] = 0.f; }
        }
    }
    const float* xp = x + (size_t)(b * CC + c) * TV;
    for (int idx = tid; idx < TT_ * VV; idx += 256) {
        int t = idx / VV, j = idx % VV;
        float v = xp[idx];
        xsT[j * 140 + t + 8] = v;
        xsS[j * 140 + t + 7] = v;
    }
    __syncthreads();

    int warp = tid >> 5, lane = tid & 31;
    int t0 = warp * 16;

    if (lane < VV) {
        u64 acc[8];
#pragma unroll
        for (int p = 0; p < 8; p++) acc[p] = 0ULL;

        const u64* wbase = reinterpret_cast<const u64*>(W2s) + lane;

        for (int j = 0; j < VV; j++) {
            // aligned u64 pairs: pe[m] = (xpad[t0+2m], xpad[t0+2m+1]); po[m] = (xpad[t0+2m+1], xpad[t0+2m+2])
            u64 pe[12], po[12];
            const ulonglong2* xe = reinterpret_cast<const ulonglong2*>(&xsT[j * 140 + t0]);
            const ulonglong2* xo = reinterpret_cast<const ulonglong2*>(&xsS[j * 140 + t0]);
#pragma unroll
            for (int q = 0; q < 6; q++) {
                ulonglong2 ve = xe[q]; pe[2 * q] = ve.x; pe[2 * q + 1] = ve.y;
                ulonglong2 vo = xo[q]; po[2 * q] = vo.x; po[2 * q + 1] = vo.y;
            }
            const u64* wrow = wbase + (j * TS) * VV;
#pragma unroll
            for (int k = 0; k < TS; k++) {
                u64 w2 = wrow[k * VV];                       // per-lane LDS.64, dup pair
                const u64* pr = (k & 1) ? &po[(k - 1) >> 1] : &pe[k >> 1];
#pragma unroll
                for (int p = 0; p < 8; p++) ffma2(acc[p], pr[p], w2);
            }
        }
        float* zp = g_zbuf + (size_t)(b * CC + c) * TV + lane;
#pragma unroll
        for (int p = 0; p < 8; p++) {
            zp[(t0 + 2 * p) * VV] = lo32(acc[p]);
            zp[(t0 + 2 * p + 1) * VV] = hi32(acc[p]);
        }
    }
}

// ---------------- kC: out = w3 @ z + b3, zero-MOV f32x2 via duplicated z in smem ----
// Block: 64 o x 128 tv. 8 warps; warp <-> 8 o (o0=warp*8), lane <-> 4 tv.
__global__ void __launch_bounds__(256) kC(const float* __restrict__ w3, const float* __restrict__ b3,
                                          float* __restrict__ out) {
    int b = blockIdx.y;
    int tv0 = blockIdx.x * 128;
    int tid = threadIdx.x;
    int warp = tid >> 5, lane = tid & 31;

    __shared__ __align__(16) float zsd[CC * 256];   // 64KB, [c][tv duplicated]
    __shared__ __align__(16) float w3T[CC * OUTC];  // 16KB, [c][o]

    const float* zb = g_zbuf + (size_t)b * CC * TV + tv0;
    for (int i = tid; i < CC * 32; i += 256) {          // one float4 per iter
        int c = i >> 5, q = i & 31;
        float4 v = *reinterpret_cast<const float4*>(zb + c * TV + q * 4);
        float4 a = make_float4(v.x, v.x, v.y, v.y);
        float4 d = make_float4(v.z, v.z, v.w, v.w);
        *reinterpret_cast<float4*>(&zsd[c * 256 + q * 8]) = a;
        *reinterpret_cast<float4*>(&zsd[c * 256 + q * 8 + 4]) = d;
    }
    for (int i = tid; i < CC * OUTC; i += 256) {
        int o = i >> 6, c = i & 63;                     // read w3 coalesced [o][c]
        w3T[c * OUTC + o] = w3[i];
    }
    __syncthreads();

    int o0 = warp * 8;
    u64 acc[4][4];   // [o-pair][tv q]
#pragma unroll
    for (int op = 0; op < 4; op++) {
        u64 bp = pack2(__ldg(b3 + o0 + 2 * op), __ldg(b3 + o0 + 2 * op + 1));
#pragma unroll
        for (int q = 0; q < 4; q++) acc[op][q] = bp;
    }

    const u64* zbase = reinterpret_cast<const u64*>(zsd) + lane * 4;
#pragma unroll 4
    for (int c = 0; c < CC; c++) {
        const u64* zc = zbase + c * 128;
        u64 xd0 = zc[0], xd1 = zc[1], xd2 = zc[2], xd3 = zc[3];  // 2 per-lane LDS.128
        const u64* wrow = reinterpret_cast<const u64*>(&w3T[c * OUTC + o0]);  // broadcast
        u64 w01 = wrow[0], w23 = wrow[1], w45 = wrow[2], w67 = wrow[3];
        ffma2(acc[0][0], xd0, w01); ffma2(acc[0][1], xd1, w01);
        ffma2(acc[0][2], xd2, w01); ffma2(acc[0][3], xd3, w01);
        ffma2(acc[1][0], xd0, w23); ffma2(acc[1][1], xd1, w23);
        ffma2(acc[1][2], xd2, w23); ffma2(acc[1][3], xd3, w23);
        ffma2(acc[2][0], xd0, w45); ffma2(acc[2][1], xd1, w45);
        ffma2(acc[2][2], xd2, w45); ffma2(acc[2][3], xd3, w45);
        ffma2(acc[3][0], xd0, w67); ffma2(acc[3][1], xd1, w67);
        ffma2(acc[3][2], xd2, w67); ffma2(acc[3][3], xd3, w67);
    }

    float* ob = out + (size_t)b * OUTC * TV + tv0 + lane * 4;
#pragma unroll
    for (int op = 0; op < 4; op++) {
        float4 lo, hi;
        lo.x = lo32(acc[op][0]); lo.y = lo32(acc[op][1]);
        lo.z = lo32(acc[op][2]); lo.w = lo32(acc[op][3]);
        hi.x = hi32(acc[op][0]); hi.y = hi32(acc[op][1]);
        hi.z = hi32(acc[op][2]); hi.w = hi32(acc[op][3]);
        *reinterpret_cast<float4*>(ob + (size_t)(o0 + 2 * op) * TV) = lo;
        *reinterpret_cast<float4*>(ob + (size_t)(o0 + 2 * op + 1) * TV) = hi;
    }
}

extern "C" void kernel_launch(void* const* d_in, const int* in_sizes, int n_in,
                              void* d_out, int out_size) {
    const float* x  = (const float*)d_in[0];
    const float* A  = (const float*)d_in[1];
    const float* w1 = (const float*)d_in[2];
    const float* b1 = (const float*)d_in[3];
    const float* w2 = (const float*)d_in[4];
    const float* b2 = (const float*)d_in[5];
    const float* w3 = (const float*)d_in[6];
    const float* b3 = (const float*)d_in[7];
    const float* w4 = (const float*)d_in[8];
    const float* b4 = (const float*)d_in[9];
    float* out = (float*)d_out;

    kA1<<<dim3(CC, BB), 128>>>(x);
    kA2<<<BB, 256>>>(w1, b1, w2, b2);
    kB<<<dim3(CC, BB), 256>>>(x, A, w4, b4);
    kC<<<dim3(TV / 128, BB), 256>>>(w3, b3, out);
}

// round 7
// speedup vs baseline: 1.2319x; 1.0771x over previous
#include <cuda_runtime.h>
#include <math.h>

#define BB 32
#define CC 64
#define TT_ 128
#define VV 25
#define RR 8
#define TS 9
#define OUTC 64
#define TV 3200   // TT_*VV

typedef unsigned long long u64;

// scratch (allocation-free rule: device globals)
__device__ float g_xm[BB * CC * VV];                 // mean_t x
__device__ float g_dbuf[BB * RR * VV * VV];          // d[b,r,j,i]
__device__ float g_zbuf[(size_t)BB * CC * TT_ * VV]; // z[b,c,t,i]

__device__ __forceinline__ u64 pack2(float lo, float hi) {
    u64 r;
    asm("mov.b64 %0, {%1, %2};" : "=l"(r) : "f"(lo), "f"(hi));
    return r;
}
__device__ __forceinline__ void ffma2(u64& d, u64 a, u64 b) {
    asm("fma.rn.f32x2 %0, %1, %2, %0;" : "+l"(d) : "l"(a), "l"(b));
}
__device__ __forceinline__ float lo32(u64 v) { float a,b; asm("mov.b64 {%0,%1}, %2;" : "=f"(a), "=f"(b) : "l"(v)); return a; }
__device__ __forceinline__ float hi32(u64 v) { float a,b; asm("mov.b64 {%0,%1}, %2;" : "=f"(a), "=f"(b) : "l"(v)); return b; }

// ---------------- kA1: coalesced mean over T, one block per (b,c) ----------------
__global__ void __launch_bounds__(128) kA1(const float* __restrict__ x) {
    int c = blockIdx.x, b = blockIdx.y;
    int tid = threadIdx.x;
    __shared__ float xt[TT_ * VV];
    __shared__ float part[VV * 4];

    const float* xp = x + (size_t)(b * CC + c) * TV;
    for (int i = tid; i < TT_ * VV; i += 128) xt[i] = xp[i];
    __syncthreads();

    if (tid < VV * 4) {
        int v = tid >> 2, s = tid & 3;
        float acc = 0.f;
#pragma unroll 8
        for (int t = s; t < TT_; t += 4) acc += xt[t * VV + v];
        part[tid] = acc;
    }
    __syncthreads();
    if (tid < VV) {
        float m = (part[tid * 4] + part[tid * 4 + 1] + part[tid * 4 + 2] + part[tid * 4 + 3]) * (1.f / (float)TT_);
        g_xm[(b * CC + c) * VV + tid] = m;
    }
}

// ---------------- kA2: x1/x2 + d=tanh(x1-x2), one block per b ----------------
__global__ void __launch_bounds__(256) kA2(const float* __restrict__ w1, const float* __restrict__ b1,
                                           const float* __restrict__ w2, const float* __restrict__ b2) {
    int b = blockIdx.x;
    int tid = threadIdx.x;
    __shared__ float xm[CC * VV];
    __shared__ float x1s[RR * VV];
    __shared__ float x2s[RR * VV];

    const float* xmg = g_xm + b * (CC * VV);
    for (int i = tid; i < CC * VV; i += 256) xm[i] = xmg[i];
    __syncthreads();

    for (int q = tid; q < 2 * RR * VV; q += 256) {
        int which = q / (RR * VV);
        int idx = q % (RR * VV);
        int r = idx / VV, v = idx % VV;
        const float* w = which ? w2 : w1;
        float s = 0.f;
#pragma unroll 8
        for (int c = 0; c < CC; c++) s = fmaf(w[r * CC + c], xm[c * VV + v], s);
        s += (which ? b2 : b1)[r];
        (which ? x2s : x1s)[idx] = s;
    }
    __syncthreads();

    float* db = g_dbuf + b * (RR * VV * VV);
    for (int idx = tid; idx < RR * VV * VV; idx += 256) {
        int r = idx / (VV * VV);
        int rem = idx % (VV * VV);
        int j = rem / VV, i = rem % VV;
        db[idx] = tanhf(x1s[r * VV + j] - x2s[r * VV + i]);
    }
}

// ---------------- kB: dynamic conv, plain W (per-lane LDS.32 + MOV dup) ----------------
// 256 threads (8 warps), warp w owns t in [w*16, w*16+16). lane<25 owns vertex i.
__global__ void __launch_bounds__(256, 3) kB(const float* __restrict__ x,
                                             const float* __restrict__ A,
                                             const float* __restrict__ w4, const float* __restrict__ b4) {
    int c = blockIdx.x;
    int b = blockIdx.y;
    int tid = threadIdx.x;

    __shared__ __align__(16) float Ws[VV * TS * VV];    // [j][k][i] plain, 22.5KB
    __shared__ __align__(16) float xsT[VV * 140];       // [j][s] = xpad[s],   14KB
    __shared__ __align__(16) float xsS[VV * 140];       // [j][s] = xpad[s+1], 14KB

    const float* db = g_dbuf + b * (RR * VV * VV);

    // W[j,i,k] = A[j,i] + b4[c*9+k] + sum_r w4[c*9+k, r] * d[r,j,i]
    for (int p = tid; p < VV * VV; p += 256) {
        float dr[RR];
#pragma unroll
        for (int r = 0; r < RR; r++) dr[r] = __ldg(db + r * (VV * VV) + p);
        float a = __ldg(A + p);
        int j = p / VV, i = p % VV;
#pragma unroll
        for (int k = 0; k < TS; k++) {
            int o = c * TS + k;
            float s = a + __ldg(b4 + o);
#pragma unroll
            for (int r = 0; r < RR; r++) s = fmaf(__ldg(w4 + o * RR + r), dr[r], s);
            Ws[(j * TS + k) * VV + i] = s;
        }
    }

    // stage x: xsT[j][8+t] = x[t][j] (zeros on [0,8) and [136,140));
    //          xsS[j][7+t] = x[t][j] (zeros on [0,7) and [135,140)).
    for (int idx = tid; idx < VV * 8; idx += 256) {
        int j = idx / 8, s0 = idx % 8;
        xsT[j * 140 + s0] = 0.f;
        if (s0 < 7) xsS[j * 140 + s0] = 0.f;
        if (s0 == 0) {
            xsS[j * 140 + 135] = 0.f;
#pragma unroll
            for (int q = 136; q < 140; q++) { xsT[j * 140 + q] = 0.f; xsS[j * 140 + q] = 0.f; }
        }
    }
    const float* xp = x + (size_t)(b * CC + c) * TV;
    for (int idx = tid; idx < TT_ * VV; idx += 256) {
        int t = idx / VV, j = idx % VV;
        float v = xp[idx];
        xsT[j * 140 + t + 8] = v;
        xsS[j * 140 + t + 7] = v;
    }
    __syncthreads();

    int warp = tid >> 5, lane = tid & 31;
    int t0 = warp * 16;

    if (lane < VV) {
        u64 acc[8];
#pragma unroll
        for (int p = 0; p < 8; p++) acc[p] = 0ULL;

        const float* wbase = Ws + lane;

        for (int j = 0; j < VV; j++) {
            // aligned u64 pairs: pe[m] = (xpad[t0+2m], xpad[t0+2m+1]); po[m] = (xpad[t0+2m+1], xpad[t0+2m+2])
            u64 pe[12], po[12];
            const ulonglong2* xe = reinterpret_cast<const ulonglong2*>(&xsT[j * 140 + t0]);
            const ulonglong2* xo = reinterpret_cast<const ulonglong2*>(&xsS[j * 140 + t0]);
#pragma unroll
            for (int q = 0; q < 6; q++) {
                ulonglong2 ve = xe[q]; pe[2 * q] = ve.x; pe[2 * q + 1] = ve.y;
                ulonglong2 vo = xo[q]; po[2 * q] = vo.x; po[2 * q + 1] = vo.y;
            }
            const float* wrow = wbase + (j * TS) * VV;
#pragma unroll
            for (int k = 0; k < TS; k++) {
                float w = wrow[k * VV];                 // per-lane LDS.32 (1 wavefront)
                u64 w2 = pack2(w, w);                   // 1 MOV (alu pipe)
                const u64* pr = (k & 1) ? &po[(k - 1) >> 1] : &pe[k >> 1];
#pragma unroll
                for (int p = 0; p < 8; p++) ffma2(acc[p], pr[p], w2);
            }
        }
        float* zp = g_zbuf + (size_t)(b * CC + c) * TV + lane;
#pragma unroll
        for (int p = 0; p < 8; p++) {
            zp[(t0 + 2 * p) * VV] = lo32(acc[p]);
            zp[(t0 + 2 * p + 1) * VV] = hi32(acc[p]);
        }
    }
}

// ---------------- kC: out = w3 @ z + b3 ----------------
// z PLAIN in smem (per-lane stream, natural tv-pairs); w3 DUPLICATED (broadcast LDS.64).
// Block: 64 o x 128 tv. 8 warps; warp <-> 8 o (o0=warp*8), lane <-> 4 tv (2 pairs).
__global__ void __launch_bounds__(256, 3) kC(const float* __restrict__ w3, const float* __restrict__ b3,
                                             float* __restrict__ out) {
    int b = blockIdx.y;
    int tv0 = blockIdx.x * 128;
    int tid = threadIdx.x;
    int warp = tid >> 5, lane = tid & 31;

    __shared__ __align__(16) float zs[CC * 128];     // 32KB, [c][tv] plain
    __shared__ __align__(16) float2 w3d[CC * OUTC];  // 32KB, [c][o] duplicated

    const float* zb = g_zbuf + (size_t)b * CC * TV + tv0;
    for (int i = tid; i < CC * 32; i += 256) {
        int c = i >> 5, q = i & 31;
        *reinterpret_cast<float4*>(&zs[c * 128 + q * 4]) =
            *reinterpret_cast<const float4*>(zb + c * TV + q * 4);
    }
    for (int i = tid; i < CC * OUTC; i += 256) {
        int o = i >> 6, c = i & 63;                  // read w3 coalesced [o][c]
        float w = w3[i];
        w3d[c * OUTC + o] = make_float2(w, w);
    }
    __syncthreads();

    int o0 = warp * 8;
    u64 acc[8][2];   // [oo][tv-pair]
#pragma unroll
    for (int oo = 0; oo < 8; oo++) {
        float bb = __ldg(b3 + o0 + oo);
        u64 bp = pack2(bb, bb);
        acc[oo][0] = bp; acc[oo][1] = bp;
    }

    const u64* zbase = reinterpret_cast<const u64*>(zs) + lane * 2;   // 2 pairs = 4 tv
    const u64* wbase = reinterpret_cast<const u64*>(w3d) + o0;
#pragma unroll 4
    for (int c = 0; c < CC; c++) {
        u64 x0, x1;
        {   // one per-lane LDS.128 -> two natural tv-pairs
            ulonglong2 v = *reinterpret_cast<const ulonglong2*>(zbase + c * 64);
            x0 = v.x; x1 = v.y;
        }
        const u64* wrow = wbase + c * OUTC;   // broadcast dup-pairs, 1 wf each
#pragma unroll
        for (int oo = 0; oo < 8; oo++) {
            u64 w2 = wrow[oo];
            ffma2(acc[oo][0], x0, w2);
            ffma2(acc[oo][1], x1, w2);
        }
    }

    float* ob = out + (size_t)b * OUTC * TV + tv0 + lane * 4;
#pragma unroll
    for (int oo = 0; oo < 8; oo++) {
        float4 v;
        v.x = lo32(acc[oo][0]); v.y = hi32(acc[oo][0]);
        v.z = lo32(acc[oo][1]); v.w = hi32(acc[oo][1]);
        *reinterpret_cast<float4*>(ob + (size_t)(o0 + oo) * TV) = v;
    }
}

extern "C" void kernel_launch(void* const* d_in, const int* in_sizes, int n_in,
                              void* d_out, int out_size) {
    const float* x  = (const float*)d_in[0];
    const float* A  = (const float*)d_in[1];
    const float* w1 = (const float*)d_in[2];
    const float* b1 = (const float*)d_in[3];
    const float* w2 = (const float*)d_in[4];
    const float* b2 = (const float*)d_in[5];
    const float* w3 = (const float*)d_in[6];
    const float* b3 = (const float*)d_in[7];
    const float* w4 = (const float*)d_in[8];
    const float* b4 = (const float*)d_in[9];
    float* out = (float*)d_out;

    kA1<<<dim3(CC, BB), 128>>>(x);
    kA2<<<BB, 256>>>(w1, b1, w2, b2);
    kB<<<dim3(CC, BB), 256>>>(x, A, w4, b4);
    kC<<<dim3(TV / 128, BB), 256>>>(w3, b3, out);
}